// round 6
// baseline (speedup 1.0000x reference)
#include <cuda_runtime.h>
#include <cuda_bf16.h>
#include <cstdint>

// Problem constants
#define NUM_IMAGES 16384
#define NUM_EXPERTS 64
#define D_MODEL 4096

// Combine-kernel tiling: smaller d-chunk -> 2 CTAs resident per SM
#define CHUNK 256                         // floats of d per chunk
#define NCHUNK (D_MODEL / CHUNK)          // 16
#define ROWTILES 18
#define ROWS_PER_TILE ((NUM_IMAGES + ROWTILES - 1) / ROWTILES)  // 911
#define CTHREADS 512
#define COLS4 (CHUNK / 4)                 // 64 float4 per row-chunk
#define RSTEP (CTHREADS / COLS4)          // 8 rows per inner iteration

// Scratch: per-row routing info {g0, g1, bitcast(e0), bitcast(e1)}  (256 KB)
__device__ float4 g_routes[NUM_IMAGES];

// ---------------------------------------------------------------------------
// Kernel 1: extract the (at most) 2 nonzero gate entries per row.
// One warp per row: lanes cover experts [lane] and [lane+32].
// ---------------------------------------------------------------------------
__global__ void moe_route_kernel(const float* __restrict__ gates) {
    int warp = (blockIdx.x * blockDim.x + threadIdx.x) >> 5;
    int lane = threadIdx.x & 31;
    if (warp >= NUM_IMAGES) return;

    const float* row = gates + (size_t)warp * NUM_EXPERTS;
    float v0 = row[lane];
    float v1 = row[lane + 32];

    unsigned m0 = __ballot_sync(0xffffffffu, v0 != 0.0f);
    unsigned m1 = __ballot_sync(0xffffffffu, v1 != 0.0f);
    unsigned long long mask = (unsigned long long)m0 |
                              ((unsigned long long)m1 << 32);

    int e0 = 0, e1 = 0;
    if (mask) {
        e0 = __ffsll((long long)mask) - 1;
        unsigned long long rest = mask & (mask - 1);
        e1 = rest ? (__ffsll((long long)rest) - 1) : e0;
    }
    // e0/e1 are warp-uniform: fetch their gate values via shuffles
    float a0 = __shfl_sync(0xffffffffu, v0, e0 & 31);
    float b0 = __shfl_sync(0xffffffffu, v1, e0 & 31);
    float g0 = (e0 < 32) ? a0 : b0;
    float a1 = __shfl_sync(0xffffffffu, v0, e1 & 31);
    float b1 = __shfl_sync(0xffffffffu, v1, e1 & 31);
    float g1 = (e1 < 32) ? a1 : b1;
    if (e1 == e0) g1 = 0.0f;       // degenerate (<2 nonzeros) safety
    if (mask == 0ull) { g0 = 0.0f; g1 = 0.0f; }

    if (lane == 0)
        g_routes[warp] = make_float4(g0, g1, __int_as_float(e0), __int_as_float(e1));
}

// ---------------------------------------------------------------------------
// Kernel 2: combine. Each CTA owns (d-chunk, row-tile).
//   smem: E slab [64][CHUNK] floats (64 KB) + tile routes (14.6 KB) ~= 80 KB.
//   __launch_bounds__(512, 2): 2 CTAs/SM -> 32 resident warps (50% occ).
// ---------------------------------------------------------------------------
__global__ __launch_bounds__(CTHREADS, 2)
void moe_combine_kernel(const float* __restrict__ E, float* __restrict__ out) {
    extern __shared__ float smem[];
    float*  eslab = smem;                                   // [64][CHUNK]
    float4* rts   = (float4*)(smem + NUM_EXPERTS * CHUNK);  // [ROWS_PER_TILE]

    const int chunk = blockIdx.x % NCHUNK;
    const int tile  = blockIdx.x / NCHUNK;
    const int row0  = tile * ROWS_PER_TILE;
    const int rend  = min(row0 + ROWS_PER_TILE, NUM_IMAGES);
    const int nrows = rend - row0;
    const int tid   = threadIdx.x;

    // Stage E slab: 64 experts x CHUNK floats of this d-chunk
    const int slab_f4 = NUM_EXPERTS * COLS4;   // 4096 float4
    for (int idx = tid; idx < slab_f4; idx += CTHREADS) {
        int e = idx / COLS4;
        int c = idx & (COLS4 - 1);
        float4 v = __ldg((const float4*)(E + (size_t)e * D_MODEL + chunk * CHUNK) + c);
        ((float4*)(eslab + e * CHUNK))[c] = v;
    }
    // Stage this tile's routes into smem (kills per-row L2-latency chain)
    for (int i = tid; i < nrows; i += CTHREADS)
        rts[i] = g_routes[row0 + i];
    __syncthreads();

    const int col = tid & (COLS4 - 1);   // 0..63
    const int sub = tid >> 6;            // 0..7  (row within iteration group)

    float* outbase = out + (size_t)row0 * D_MODEL + chunk * CHUNK;

    #pragma unroll 2
    for (int r = sub; r < nrows; r += RSTEP) {
        float4 rt = rts[r];                       // warp-broadcast LDS
        int e0 = __float_as_int(rt.z);
        int e1 = __float_as_int(rt.w);
        float4 a = ((const float4*)(eslab + e0 * CHUNK))[col];
        float4 b = ((const float4*)(eslab + e1 * CHUNK))[col];
        float4 o;
        o.x = rt.x * a.x + rt.y * b.x;
        o.y = rt.x * a.y + rt.y * b.y;
        o.z = rt.x * a.z + rt.y * b.z;
        o.w = rt.x * a.w + rt.y * b.w;
        // streaming store: output is written once, never re-read
        __stcs((float4*)(outbase + (size_t)r * D_MODEL) + col, o);
    }
}

// ---------------------------------------------------------------------------
extern "C" void kernel_launch(void* const* d_in, const int* in_sizes, int n_in,
                              void* d_out, int out_size) {
    // Identify inputs by element count (defensive): E = 64*4096, gates = 16384*64
    const float* E     = (const float*)d_in[0];
    const float* gates = (const float*)d_in[1];
    if (in_sizes[0] == NUM_IMAGES * NUM_EXPERTS) {
        gates = (const float*)d_in[0];
        E     = (const float*)d_in[1];
    }
    float* out = (float*)d_out;

    // Routing: one warp per row, 8 warps per 256-thread block
    {
        int rows_per_block = 256 / 32;
        int blocks = (NUM_IMAGES + rows_per_block - 1) / rows_per_block;
        moe_route_kernel<<<blocks, 256>>>(gates);
    }

    // Combine: 16 chunks x 18 row tiles = 288 CTAs (2 CTAs per SM)
    {
        static int smem_set = 0;
        int smem_bytes = NUM_EXPERTS * CHUNK * (int)sizeof(float)
                       + ROWS_PER_TILE * (int)sizeof(float4);
        if (!smem_set) {
            cudaFuncSetAttribute(moe_combine_kernel,
                                 cudaFuncAttributeMaxDynamicSharedMemorySize,
                                 smem_bytes);
            smem_set = 1;
        }
        moe_combine_kernel<<<NCHUNK * ROWTILES, CTHREADS, smem_bytes>>>(E, out);
    }
}

// round 7
// speedup vs baseline: 1.3267x; 1.3267x over previous
#include <cuda_runtime.h>
#include <cuda_bf16.h>
#include <cstdint>

// Problem constants
#define NUM_IMAGES 16384
#define NUM_EXPERTS 64
#define D_MODEL 4096

// Combine-kernel tiling
#define CHUNK 512                         // floats of d per chunk
#define NCHUNK (D_MODEL / CHUNK)          // 8
#define ROWTILES 18
#define ROWS_PER_TILE ((NUM_IMAGES + ROWTILES - 1) / ROWTILES)  // 911
#define CTHREADS 512
#define NWARPS (CTHREADS / 32)            // 16
#define COLS4 (CHUNK / 4)                 // 128 float4 per row-chunk

// Scratch: per-row routing info {g0, g1, bitcast(e0), bitcast(e1)}  (256 KB)
__device__ float4 g_routes[NUM_IMAGES];

// ---------------------------------------------------------------------------
// Kernel 1: extract the (at most) 2 nonzero gate entries per row.
// One warp per row: lanes cover experts [lane] and [lane+32].
// ---------------------------------------------------------------------------
__global__ void moe_route_kernel(const float* __restrict__ gates) {
    int warp = (blockIdx.x * blockDim.x + threadIdx.x) >> 5;
    int lane = threadIdx.x & 31;
    if (warp >= NUM_IMAGES) return;

    const float* row = gates + (size_t)warp * NUM_EXPERTS;
    float v0 = row[lane];
    float v1 = row[lane + 32];

    unsigned m0 = __ballot_sync(0xffffffffu, v0 != 0.0f);
    unsigned m1 = __ballot_sync(0xffffffffu, v1 != 0.0f);
    unsigned long long mask = (unsigned long long)m0 |
                              ((unsigned long long)m1 << 32);

    int e0 = 0, e1 = 0;
    if (mask) {
        e0 = __ffsll((long long)mask) - 1;
        unsigned long long rest = mask & (mask - 1);
        e1 = rest ? (__ffsll((long long)rest) - 1) : e0;
    }
    // e0/e1 are warp-uniform: fetch their gate values via shuffles
    float a0 = __shfl_sync(0xffffffffu, v0, e0 & 31);
    float b0 = __shfl_sync(0xffffffffu, v1, e0 & 31);
    float g0 = (e0 < 32) ? a0 : b0;
    float a1 = __shfl_sync(0xffffffffu, v0, e1 & 31);
    float b1 = __shfl_sync(0xffffffffu, v1, e1 & 31);
    float g1 = (e1 < 32) ? a1 : b1;
    if (e1 == e0) g1 = 0.0f;       // degenerate (<2 nonzeros) safety
    if (mask == 0ull) { g0 = 0.0f; g1 = 0.0f; }

    if (lane == 0)
        g_routes[warp] = make_float4(g0, g1, __int_as_float(e0), __int_as_float(e1));
}

// ---------------------------------------------------------------------------
// Kernel 2: combine. Each CTA owns (d-chunk, row-tile).
//   smem: E slab [64][CHUNK] floats (128 KB) + tile routes (14.6 KB).
//   Mapping: warp-per-row, each lane handles 4 column pieces (stride 32 f4).
//   Route for next row is prefetched -> 8 independent LDS.128 per route read.
// ---------------------------------------------------------------------------
__global__ __launch_bounds__(CTHREADS, 1)
void moe_combine_kernel(const float* __restrict__ E, float* __restrict__ out) {
    extern __shared__ float smem[];
    float*  eslab = smem;                                   // [64][CHUNK]
    float4* rts   = (float4*)(smem + NUM_EXPERTS * CHUNK);  // [ROWS_PER_TILE]

    const int chunk = blockIdx.x % NCHUNK;
    const int tile  = blockIdx.x / NCHUNK;
    const int row0  = tile * ROWS_PER_TILE;
    const int rend  = min(row0 + ROWS_PER_TILE, NUM_IMAGES);
    const int nrows = rend - row0;
    const int tid   = threadIdx.x;

    // Stage E slab: 64 experts x CHUNK floats of this d-chunk
    const int slab_f4 = NUM_EXPERTS * COLS4;   // 8192 float4
    for (int idx = tid; idx < slab_f4; idx += CTHREADS) {
        int e = idx >> 7;          // / COLS4 (=128)
        int c = idx & (COLS4 - 1);
        float4 v = __ldg((const float4*)(E + (size_t)e * D_MODEL + chunk * CHUNK) + c);
        ((float4*)(eslab + e * CHUNK))[c] = v;
    }
    // Stage this tile's routes into smem
    for (int i = tid; i < nrows; i += CTHREADS)
        rts[i] = g_routes[row0 + i];
    __syncthreads();

    const int wid  = tid >> 5;   // 0..15: warp handles rows wid, wid+16, ...
    const int lane = tid & 31;

    float* outbase = out + (size_t)row0 * D_MODEL + chunk * CHUNK;

    // Software-pipelined over rows: rt for row r is loaded one iteration early.
    float4 rt = rts[(wid < nrows) ? wid : 0];
    for (int r = wid; r < nrows; r += NWARPS) {
        // Prefetch next row's route (clamped; value unused past the last row)
        int rn = r + NWARPS;
        float4 rt_next = rts[(rn < nrows) ? rn : (nrows - 1)];

        int e0 = __float_as_int(rt.z);
        int e1 = __float_as_int(rt.w);
        const float4* A = (const float4*)(eslab + e0 * CHUNK);
        const float4* B = (const float4*)(eslab + e1 * CHUNK);

        // 8 independent LDS.128 — deep MLP behind one route read
        float4 a0 = A[lane];      float4 b0 = B[lane];
        float4 a1 = A[lane + 32]; float4 b1 = B[lane + 32];
        float4 a2 = A[lane + 64]; float4 b2 = B[lane + 64];
        float4 a3 = A[lane + 96]; float4 b3 = B[lane + 96];

        const float g0 = rt.x, g1 = rt.y;
        float4 o0, o1, o2, o3;
        o0.x = fmaf(g0, a0.x, g1 * b0.x); o0.y = fmaf(g0, a0.y, g1 * b0.y);
        o0.z = fmaf(g0, a0.z, g1 * b0.z); o0.w = fmaf(g0, a0.w, g1 * b0.w);
        o1.x = fmaf(g0, a1.x, g1 * b1.x); o1.y = fmaf(g0, a1.y, g1 * b1.y);
        o1.z = fmaf(g0, a1.z, g1 * b1.z); o1.w = fmaf(g0, a1.w, g1 * b1.w);
        o2.x = fmaf(g0, a2.x, g1 * b2.x); o2.y = fmaf(g0, a2.y, g1 * b2.y);
        o2.z = fmaf(g0, a2.z, g1 * b2.z); o2.w = fmaf(g0, a2.w, g1 * b2.w);
        o3.x = fmaf(g0, a3.x, g1 * b3.x); o3.y = fmaf(g0, a3.y, g1 * b3.y);
        o3.z = fmaf(g0, a3.z, g1 * b3.z); o3.w = fmaf(g0, a3.w, g1 * b3.w);

        float4* orow = (float4*)(outbase + (size_t)r * D_MODEL);
        __stcs(orow + lane,      o0);
        __stcs(orow + lane + 32, o1);
        __stcs(orow + lane + 64, o2);
        __stcs(orow + lane + 96, o3);

        rt = rt_next;
    }
}

// ---------------------------------------------------------------------------
extern "C" void kernel_launch(void* const* d_in, const int* in_sizes, int n_in,
                              void* d_out, int out_size) {
    // Identify inputs by element count (defensive): E = 64*4096, gates = 16384*64
    const float* E     = (const float*)d_in[0];
    const float* gates = (const float*)d_in[1];
    if (in_sizes[0] == NUM_IMAGES * NUM_EXPERTS) {
        gates = (const float*)d_in[0];
        E     = (const float*)d_in[1];
    }
    float* out = (float*)d_out;

    // Routing: one warp per row, 8 warps per 256-thread block
    {
        int rows_per_block = 256 / 32;
        int blocks = (NUM_IMAGES + rows_per_block - 1) / rows_per_block;
        moe_route_kernel<<<blocks, 256>>>(gates);
    }

    // Combine: 8 chunks x 18 row tiles = 144 CTAs (one wave)
    {
        static int smem_set = 0;
        int smem_bytes = NUM_EXPERTS * CHUNK * (int)sizeof(float)
                       + ROWS_PER_TILE * (int)sizeof(float4);
        if (!smem_set) {
            cudaFuncSetAttribute(moe_combine_kernel,
                                 cudaFuncAttributeMaxDynamicSharedMemorySize,
                                 smem_bytes);
            smem_set = 1;
        }
        moe_combine_kernel<<<NCHUNK * ROWTILES, CTHREADS, smem_bytes>>>(E, out);
    }
}

// round 8
// speedup vs baseline: 1.3375x; 1.0082x over previous
#include <cuda_runtime.h>
#include <cuda_bf16.h>
#include <cstdint>

// Problem constants
#define NUM_IMAGES 16384
#define NUM_EXPERTS 64
#define D_MODEL 4096

// Combine-kernel tiling
#define CHUNK 512                         // floats of d per chunk
#define NCHUNK (D_MODEL / CHUNK)          // 8
#define ROWTILES 18
#define ROWS_PER_TILE ((NUM_IMAGES + ROWTILES - 1) / ROWTILES)  // 911
#define CTHREADS 512
#define NWARPS (CTHREADS / 32)            // 16
#define COLS4 (CHUNK / 4)                 // 128 float4 per row-chunk

// Scratch: per-row routing info {g0, g1, bitcast(e0), bitcast(e1)}  (256 KB)
__device__ float4 g_routes[NUM_IMAGES];

// ---------------------------------------------------------------------------
// Kernel 1: extract the (at most) 2 nonzero gate entries per row.
// ---------------------------------------------------------------------------
__global__ void moe_route_kernel(const float* __restrict__ gates) {
    int warp = (blockIdx.x * blockDim.x + threadIdx.x) >> 5;
    int lane = threadIdx.x & 31;
    if (warp >= NUM_IMAGES) return;

    const float* row = gates + (size_t)warp * NUM_EXPERTS;
    float v0 = row[lane];
    float v1 = row[lane + 32];

    unsigned m0 = __ballot_sync(0xffffffffu, v0 != 0.0f);
    unsigned m1 = __ballot_sync(0xffffffffu, v1 != 0.0f);
    unsigned long long mask = (unsigned long long)m0 |
                              ((unsigned long long)m1 << 32);

    int e0 = 0, e1 = 0;
    if (mask) {
        e0 = __ffsll((long long)mask) - 1;
        unsigned long long rest = mask & (mask - 1);
        e1 = rest ? (__ffsll((long long)rest) - 1) : e0;
    }
    float a0 = __shfl_sync(0xffffffffu, v0, e0 & 31);
    float b0 = __shfl_sync(0xffffffffu, v1, e0 & 31);
    float g0 = (e0 < 32) ? a0 : b0;
    float a1 = __shfl_sync(0xffffffffu, v0, e1 & 31);
    float b1 = __shfl_sync(0xffffffffu, v1, e1 & 31);
    float g1 = (e1 < 32) ? a1 : b1;
    if (e1 == e0) g1 = 0.0f;
    if (mask == 0ull) { g0 = 0.0f; g1 = 0.0f; }

    if (lane == 0)
        g_routes[warp] = make_float4(g0, g1, __int_as_float(e0), __int_as_float(e1));
}

// ---------------------------------------------------------------------------
// Process one row: 4 column pieces per lane (8 LDS.128 + 4 STG.128).
// ---------------------------------------------------------------------------
__device__ __forceinline__ void process_row(
    const float* eslab, float* outbase, int r, float4 rt, int lane)
{
    int e0 = __float_as_int(rt.z);
    int e1 = __float_as_int(rt.w);
    const float4* A = (const float4*)(eslab + e0 * CHUNK);
    const float4* B = (const float4*)(eslab + e1 * CHUNK);

    float4 a0 = A[lane];      float4 b0 = B[lane];
    float4 a1 = A[lane + 32]; float4 b1 = B[lane + 32];
    float4 a2 = A[lane + 64]; float4 b2 = B[lane + 64];
    float4 a3 = A[lane + 96]; float4 b3 = B[lane + 96];

    const float g0 = rt.x, g1 = rt.y;
    float4 o0, o1, o2, o3;
    o0.x = fmaf(g0, a0.x, g1 * b0.x); o0.y = fmaf(g0, a0.y, g1 * b0.y);
    o0.z = fmaf(g0, a0.z, g1 * b0.z); o0.w = fmaf(g0, a0.w, g1 * b0.w);
    o1.x = fmaf(g0, a1.x, g1 * b1.x); o1.y = fmaf(g0, a1.y, g1 * b1.y);
    o1.z = fmaf(g0, a1.z, g1 * b1.z); o1.w = fmaf(g0, a1.w, g1 * b1.w);
    o2.x = fmaf(g0, a2.x, g1 * b2.x); o2.y = fmaf(g0, a2.y, g1 * b2.y);
    o2.z = fmaf(g0, a2.z, g1 * b2.z); o2.w = fmaf(g0, a2.w, g1 * b2.w);
    o3.x = fmaf(g0, a3.x, g1 * b3.x); o3.y = fmaf(g0, a3.y, g1 * b3.y);
    o3.z = fmaf(g0, a3.z, g1 * b3.z); o3.w = fmaf(g0, a3.w, g1 * b3.w);

    float4* orow = (float4*)(outbase + (size_t)r * D_MODEL);
    __stcs(orow + lane,      o0);
    __stcs(orow + lane + 32, o1);
    __stcs(orow + lane + 64, o2);
    __stcs(orow + lane + 96, o3);
}

// ---------------------------------------------------------------------------
// Kernel 2: combine. Each CTA owns (d-chunk, row-tile).
//   smem: E slab [64][CHUNK] floats (128 KB) + tile routes (14.6 KB).
//   Warp-per-row, 2 rows per iteration -> 24 in-flight memops per warp.
// ---------------------------------------------------------------------------
__global__ __launch_bounds__(CTHREADS, 1)
void moe_combine_kernel(const float* __restrict__ E, float* __restrict__ out) {
    extern __shared__ float smem[];
    float*  eslab = smem;                                   // [64][CHUNK]
    float4* rts   = (float4*)(smem + NUM_EXPERTS * CHUNK);  // [ROWS_PER_TILE]

    const int chunk = blockIdx.x % NCHUNK;
    const int tile  = blockIdx.x / NCHUNK;
    const int row0  = tile * ROWS_PER_TILE;
    const int rend  = min(row0 + ROWS_PER_TILE, NUM_IMAGES);
    const int nrows = rend - row0;
    const int tid   = threadIdx.x;

    // Stage E slab: 64 experts x CHUNK floats of this d-chunk
    const int slab_f4 = NUM_EXPERTS * COLS4;   // 8192 float4
    for (int idx = tid; idx < slab_f4; idx += CTHREADS) {
        int e = idx >> 7;          // / COLS4 (=128)
        int c = idx & (COLS4 - 1);
        float4 v = __ldg((const float4*)(E + (size_t)e * D_MODEL + chunk * CHUNK) + c);
        ((float4*)(eslab + e * CHUNK))[c] = v;
    }
    // Stage this tile's routes into smem
    for (int i = tid; i < nrows; i += CTHREADS)
        rts[i] = g_routes[row0 + i];
    __syncthreads();

    const int wid  = tid >> 5;   // 0..15: warp handles rows wid, wid+16, ...
    const int lane = tid & 31;

    float* outbase = out + (size_t)row0 * D_MODEL + chunk * CHUNK;
    const int last = nrows - 1;

    // Prefetched routes for the current row pair
    float4 rt0 = rts[(wid          <= last) ? wid          : last];
    float4 rt1 = rts[(wid + NWARPS <= last) ? wid + NWARPS : last];

    int r = wid;
    for (; r + NWARPS < nrows; r += 2 * NWARPS) {
        // Prefetch next pair's routes
        int rn0 = r + 2 * NWARPS, rn1 = r + 3 * NWARPS;
        float4 nrt0 = rts[(rn0 <= last) ? rn0 : last];
        float4 nrt1 = rts[(rn1 <= last) ? rn1 : last];

        process_row(eslab, outbase, r,          rt0, lane);
        process_row(eslab, outbase, r + NWARPS, rt1, lane);

        rt0 = nrt0; rt1 = nrt1;
    }
    if (r < nrows)
        process_row(eslab, outbase, r, rt0, lane);
}

// ---------------------------------------------------------------------------
extern "C" void kernel_launch(void* const* d_in, const int* in_sizes, int n_in,
                              void* d_out, int out_size) {
    // Identify inputs by element count (defensive): E = 64*4096, gates = 16384*64
    const float* E     = (const float*)d_in[0];
    const float* gates = (const float*)d_in[1];
    if (in_sizes[0] == NUM_IMAGES * NUM_EXPERTS) {
        gates = (const float*)d_in[0];
        E     = (const float*)d_in[1];
    }
    float* out = (float*)d_out;

    // Routing: one warp per row, 8 warps per 256-thread block
    {
        int rows_per_block = 256 / 32;
        int blocks = (NUM_IMAGES + rows_per_block - 1) / rows_per_block;
        moe_route_kernel<<<blocks, 256>>>(gates);
    }

    // Combine: 8 chunks x 18 row tiles = 144 CTAs (one wave)
    {
        static int smem_set = 0;
        int smem_bytes = NUM_EXPERTS * CHUNK * (int)sizeof(float)
                       + ROWS_PER_TILE * (int)sizeof(float4);
        if (!smem_set) {
            cudaFuncSetAttribute(moe_combine_kernel,
                                 cudaFuncAttributeMaxDynamicSharedMemorySize,
                                 smem_bytes);
            smem_set = 1;
        }
        moe_combine_kernel<<<NCHUNK * ROWTILES, CTHREADS, smem_bytes>>>(E, out);
    }
}